// round 6
// baseline (speedup 1.0000x reference)
#include <cuda_runtime.h>
#include <cstdint>

// FilterTransform: cascaded biquads (fixed HP + random coeffs) over time,
// x[4096,16000] and n[4096,16000] -> out [8192,16000].
//
// R6: depth-3 cp.async smem pipeline (wait_group 2 -> prefetch distance 2
// tiles, DRAM latency fully hidden) + rolling LDS prefetch in the compute
// loop. Stage 1 restored to exact DF2T (R5's DF-I high-pass cost 4 decades
// of accuracy: pole |z|~0.998); stage 2 stays DF-I (poles <= 0.83, benign).

static constexpr int T_LEN   = 16000;
static constexpr int HALF    = 4096;
static constexpr int SEG     = 32;                  // float4 per row per tile (512B)
static constexpr int NTILES  = (T_LEN / 4) / SEG;   // 125
static constexpr int ROWS    = 28;                  // rows per block
static constexpr int XBLOCKS = (HALF + ROWS - 1) / ROWS;  // 147
static constexpr int PAD     = 1;                   // +1 float4 -> conflict-free LDS

__device__ __forceinline__ void cp_async16(uint32_t saddr, const void* gptr) {
    asm volatile("cp.async.cg.shared.global [%0], [%1], 16;"
                 :: "r"(saddr), "l"(gptr) : "memory");
}
__device__ __forceinline__ void cp_commit() {
    asm volatile("cp.async.commit_group;" ::: "memory");
}
__device__ __forceinline__ void cp_wait2() {
    asm volatile("cp.async.wait_group 2;" ::: "memory");
}

__global__ __launch_bounds__(32)
void biquad_cascade_kernel(const float* __restrict__ x,
                           const float* __restrict__ n,
                           const float* __restrict__ a_x,
                           const float* __restrict__ b_x,
                           const float* __restrict__ a_n,
                           const float* __restrict__ b_n,
                           float* __restrict__ out)
{
    __shared__ float4 tile[3][ROWS][SEG + PAD];

    const int lane = threadIdx.x;
    const bool is_x = (blockIdx.x < XBLOCKS);
    const int bi = is_x ? blockIdx.x : blockIdx.x - XBLOCKS;
    const int rowbase = bi * ROWS;
    const int nrows = (HALF - rowbase) < ROWS ? (HALF - rowbase) : ROWS;

    const float* inbase = is_x ? (x + (size_t)rowbase * T_LEN)
                               : (n + (size_t)rowbase * T_LEN);
    float* outbase = out + (size_t)(is_x ? rowbase : rowbase + HALF) * T_LEN;

    float b0, b1, na0, na1;
    if (is_x) { na0 = -a_x[0]; na1 = -a_x[1]; b0 = b_x[0]; b1 = b_x[1]; }
    else      { na0 = -a_n[0]; na1 = -a_n[1]; b0 = b_n[0]; b1 = b_n[1]; }

    // Stage 1 (HP) DF2T state; stage 2 DF-I histories (u = stage-1 output).
    float m0 = 0.f, m1 = 0.f;
    float u1 = 0.f, u2 = 0.f, v1 = 0.f, v2 = 0.f;

    auto issue_tile = [&](int g, int buf) {
        const float* src = inbase + (size_t)g * (SEG * 4) + lane * 4;
        for (int i = 0; i < nrows; i++) {
            uint32_t saddr = (uint32_t)__cvta_generic_to_shared(&tile[buf][i][lane]);
            cp_async16(saddr, src + (size_t)i * T_LEN);
        }
    };

    issue_tile(0, 0); cp_commit();
    issue_tile(1, 1); cp_commit();
    issue_tile(2, 2); cp_commit();

    const bool active = (lane < nrows);

    int buf = 0;
    for (int g = 0; g < NTILES; g++) {
        cp_wait2();            // tile g landed (<=2 newer groups pending)
        __syncwarp();

        if (active) {
            float4* myrow = &tile[buf][lane][0];
            float4 nxt = myrow[0];
            #pragma unroll 8
            for (int j = 0; j < SEG; j++) {
                float4 vin = nxt;
                if (j + 1 < SEG) nxt = myrow[j + 1];   // rolling LDS prefetch
                float xs[4] = {vin.x, vin.y, vin.z, vin.w};
                float ys[4];
                #pragma unroll
                for (int k = 0; k < 4; k++) {
                    const float xv = xs[k];
                    // Stage 1: exact DF2T high-pass (matches reference recurrence)
                    const float y1 = xv + m0;
                    m0 = fmaf(1.99599f, y1, fmaf(-2.0f, xv, m1));
                    m1 = fmaf(-0.996f, y1, xv);
                    // Stage 2: DF-I with runtime coeffs (well-damped poles)
                    float s = fmaf(b0, u1, y1);
                    s = fmaf(b1, u2, s);
                    s = fmaf(na1, v2, s);
                    const float v = fmaf(na0, v1, s);
                    u2 = u1; u1 = y1;
                    v2 = v1; v1 = v;
                    ys[k] = v;
                }
                myrow[j] = make_float4(ys[0], ys[1], ys[2], ys[3]);
            }
        }
        __syncwarp();

        // Coalesced store: 512B STG.128 per row.
        {
            float* dst = outbase + (size_t)g * (SEG * 4) + lane * 4;
            for (int i = 0; i < nrows; i++) {
                float4 v = tile[buf][i][lane];
                *(float4*)(dst + (size_t)i * T_LEN) = v;
            }
        }
        __syncwarp();          // all lanes done reading buf before refill

        if (g + 3 < NTILES) issue_tile(g + 3, buf);
        cp_commit();           // exactly one group per iteration

        buf = (buf == 2) ? 0 : buf + 1;
    }
}

extern "C" void kernel_launch(void* const* d_in, const int* in_sizes, int n_in,
                              void* d_out, int out_size)
{
    const float* x   = (const float*)d_in[0];
    const float* n   = (const float*)d_in[1];
    const float* a_x = (const float*)d_in[2];
    const float* b_x = (const float*)d_in[3];
    const float* a_n = (const float*)d_in[4];
    const float* b_n = (const float*)d_in[5];
    float* out = (float*)d_out;

    biquad_cascade_kernel<<<2 * XBLOCKS, 32>>>(x, n, a_x, b_x, a_n, b_n, out);
}

// round 7
// speedup vs baseline: 1.1791x; 1.1791x over previous
#include <cuda_runtime.h>
#include <cstdint>

// FilterTransform: cascaded biquads (fixed HP + random coeffs) over time,
// x[4096,16000] and n[4096,16000] -> out [8192,16000].
//
// R7: ROWS 28 -> 14 (586 blocks, ~4 warps/SM = one per SMSP). R6 analysis:
// per-warp issue ~90% on its SMSP while half the SMSPs sat empty; fma-pipe
// work per warp is fixed (warp-wide instrs), so more warps each carrying
// half the memory-issue overhead fills the chip. Math unchanged from R6
// (stage 1 exact DF2T with immediate coeffs, stage 2 DF-I, rel_err 6e-8).

static constexpr int T_LEN   = 16000;
static constexpr int HALF    = 4096;
static constexpr int SEG     = 32;                  // float4 per row per tile (512B)
static constexpr int NTILES  = (T_LEN / 4) / SEG;   // 125
static constexpr int ROWS    = 14;                  // rows per block
static constexpr int XBLOCKS = (HALF + ROWS - 1) / ROWS;  // 293 (last block = 8 rows)
static constexpr int PAD     = 1;                   // +1 float4 -> conflict-free LDS

__device__ __forceinline__ void cp_async16(uint32_t saddr, const void* gptr) {
    asm volatile("cp.async.cg.shared.global [%0], [%1], 16;"
                 :: "r"(saddr), "l"(gptr) : "memory");
}
__device__ __forceinline__ void cp_commit() {
    asm volatile("cp.async.commit_group;" ::: "memory");
}
__device__ __forceinline__ void cp_wait2() {
    asm volatile("cp.async.wait_group 2;" ::: "memory");
}

__global__ __launch_bounds__(32)
void biquad_cascade_kernel(const float* __restrict__ x,
                           const float* __restrict__ n,
                           const float* __restrict__ a_x,
                           const float* __restrict__ b_x,
                           const float* __restrict__ a_n,
                           const float* __restrict__ b_n,
                           float* __restrict__ out)
{
    __shared__ float4 tile[3][ROWS][SEG + PAD];

    const int lane = threadIdx.x;
    const bool is_x = (blockIdx.x < XBLOCKS);
    const int bi = is_x ? blockIdx.x : blockIdx.x - XBLOCKS;
    const int rowbase = bi * ROWS;
    const int nrows = (HALF - rowbase) < ROWS ? (HALF - rowbase) : ROWS;

    const float* inbase = is_x ? (x + (size_t)rowbase * T_LEN)
                               : (n + (size_t)rowbase * T_LEN);
    float* outbase = out + (size_t)(is_x ? rowbase : rowbase + HALF) * T_LEN;

    float b0, b1, na0, na1;
    if (is_x) { na0 = -a_x[0]; na1 = -a_x[1]; b0 = b_x[0]; b1 = b_x[1]; }
    else      { na0 = -a_n[0]; na1 = -a_n[1]; b0 = b_n[0]; b1 = b_n[1]; }

    // Stage 1 (HP) DF2T state; stage 2 DF-I histories (u = stage-1 output).
    float m0 = 0.f, m1 = 0.f;
    float u1 = 0.f, u2 = 0.f, v1 = 0.f, v2 = 0.f;

    auto issue_tile = [&](int g, int buf) {
        const float* src = inbase + (size_t)g * (SEG * 4) + lane * 4;
        for (int i = 0; i < nrows; i++) {
            uint32_t saddr = (uint32_t)__cvta_generic_to_shared(&tile[buf][i][lane]);
            cp_async16(saddr, src + (size_t)i * T_LEN);
        }
    };

    issue_tile(0, 0); cp_commit();
    issue_tile(1, 1); cp_commit();
    issue_tile(2, 2); cp_commit();

    const bool active = (lane < nrows);

    int buf = 0;
    for (int g = 0; g < NTILES; g++) {
        cp_wait2();            // tile g landed (<=2 newer groups pending)
        __syncwarp();

        if (active) {
            float4* myrow = &tile[buf][lane][0];
            float4 nxt = myrow[0];
            #pragma unroll 8
            for (int j = 0; j < SEG; j++) {
                float4 vin = nxt;
                if (j + 1 < SEG) nxt = myrow[j + 1];   // rolling LDS prefetch
                float xs[4] = {vin.x, vin.y, vin.z, vin.w};
                float ys[4];
                #pragma unroll
                for (int k = 0; k < 4; k++) {
                    const float xv = xs[k];
                    // Stage 1: exact DF2T high-pass (immediate coeffs -> FFMA-imm)
                    const float y1 = xv + m0;
                    m0 = fmaf(1.99599f, y1, fmaf(-2.0f, xv, m1));
                    m1 = fmaf(-0.996f, y1, xv);
                    // Stage 2: DF-I with runtime coeffs (well-damped poles)
                    float s = fmaf(b0, u1, y1);
                    s = fmaf(b1, u2, s);
                    s = fmaf(na1, v2, s);
                    const float v = fmaf(na0, v1, s);
                    u2 = u1; u1 = y1;
                    v2 = v1; v1 = v;
                    ys[k] = v;
                }
                myrow[j] = make_float4(ys[0], ys[1], ys[2], ys[3]);
            }
        }
        __syncwarp();

        // Coalesced store: 512B STG.128 per row.
        {
            float* dst = outbase + (size_t)g * (SEG * 4) + lane * 4;
            for (int i = 0; i < nrows; i++) {
                float4 v = tile[buf][i][lane];
                *(float4*)(dst + (size_t)i * T_LEN) = v;
            }
        }
        __syncwarp();          // all lanes done reading buf before refill

        if (g + 3 < NTILES) issue_tile(g + 3, buf);
        cp_commit();           // exactly one group per iteration

        buf = (buf == 2) ? 0 : buf + 1;
    }
}

extern "C" void kernel_launch(void* const* d_in, const int* in_sizes, int n_in,
                              void* d_out, int out_size)
{
    const float* x   = (const float*)d_in[0];
    const float* n   = (const float*)d_in[1];
    const float* a_x = (const float*)d_in[2];
    const float* b_x = (const float*)d_in[3];
    const float* a_n = (const float*)d_in[4];
    const float* b_n = (const float*)d_in[5];
    float* out = (float*)d_out;

    biquad_cascade_kernel<<<2 * XBLOCKS, 32>>>(x, n, a_x, b_x, a_n, b_n, out);
}